// round 9
// baseline (speedup 1.0000x reference)
#include <cuda_runtime.h>
#include <cstdint>

// out[b,i,j,c] = sum_k exp(-2(li-x0k)^2)*exp(-2(lj-x1k)^2)*Yb[k,c]
// GEMM: C[64 x 640] = A[64 x 1024] * Z[1024 x 640], bf16 mma m16n8k16.
#define NB    16
#define NN    1024
#define STEP  (6.0f / 63.0f)
#define EX2C  (-2.885390081777927f)   // -2*log2(e)
#define KC    64

// A in m16n8k16 a-frag layout, bf16x2 packed: u32 idx =
//   b*32768 + kstep*512 + slab*128 + lane*4 + q
__device__ __align__(16) uint32_t g_Aperm[NB * 64 * 4 * 32 * 4];
// partials in c-frag layout: [ks2][b*16+jt][nc5][slab4][lane32][4]
__device__ __align__(16) float g_part[2 * 256 * 2560];
__device__ int g_cnt[256];            // zero-init; reset by last arriver

__device__ __forceinline__ float ex2f(float x) {
    float r; asm("ex2.approx.ftz.f32 %0, %1;" : "=f"(r) : "f"(x)); return r;
}
__device__ __forceinline__ uint32_t pack_bf16(float lo, float hi) {
    uint32_t d;
    asm("cvt.rn.bf16x2.f32 %0, %1, %2;" : "=r"(d) : "f"(hi), "f"(lo));
    return d;
}
#define MMA_BF16(d, a, bb) \
    asm volatile("mma.sync.aligned.m16n8k16.row.col.f32.bf16.bf16.f32 " \
        "{%0,%1,%2,%3}, {%4,%5,%6,%7}, {%8,%9}, {%0,%1,%2,%3};" \
        : "+f"(d[0]), "+f"(d[1]), "+f"(d[2]), "+f"(d[3]) \
        : "r"(a.x), "r"(a.y), "r"(a.z), "r"(a.w), "r"(bb.x), "r"(bb.y))

// ---------- precompute A: 4 u32 per thread, one shared X load ----------
// grid 512 x 256 = 131072 threads; fields: q2|lane5|kstep6|b4
__global__ __launch_bounds__(256)
void rkhs_precomp_kernel(const float* __restrict__ X, float* __restrict__ out)
{
    int tid = blockIdx.x * blockDim.x + threadIdx.x;
    if (tid < 4096) {
        out[tid * 2 + 0] = -3.0f + (float)(tid >> 6) * STEP;
        out[tid * 2 + 1] = -3.0f + (float)(tid & 63) * STEP;
    }
    int q     = tid & 3;
    int lane  = (tid >> 2) & 31;
    int kstep = (tid >> 7) & 63;
    int b     = tid >> 13;

    int kb = kstep * 16 + ((lane & 3) << 1) + ((q >> 1) << 3);
    float4 xx = *(const float4*)(X + (size_t)(b * NN + kb) * 2); // x0[kb],x1,x0[kb+1],x1
    int rbase = (lane >> 2) + ((q & 1) << 3);
    uint32_t* dst = g_Aperm + (b * 32768 + kstep * 512 + lane * 4 + q);
#pragma unroll
    for (int slab = 0; slab < 4; ++slab) {
        float li = -3.0f + (float)(slab * 16 + rbase) * STEP;
        float d0 = li - xx.x;
        float d1 = li - xx.z;
        dst[slab * 128] = pack_bf16(ex2f(d0 * d0 * EX2C), ex2f(d1 * d1 * EX2C));
    }
}

// ---------- main: grid 512 = b(16) x jt(16) x ks(2), 256 thr ----------
#define YSTR 66
__global__ __launch_bounds__(256, 4)
void rkhs_mma_kernel(const float* __restrict__ X, const float* __restrict__ Y,
                     float* __restrict__ out)
{
    __shared__ __align__(16) uint32_t sZ[2][4 * 5 * 32 * 2];   // 2 x 5120 B
    __shared__ __align__(16) float    sYt[2][8 * YSTR];
    __shared__ __align__(16) float    sB[2][4 * YSTR];
    __shared__ int sLast;

    const int bx = blockIdx.x;
    const int ks = bx & 1;
    const int jt = (bx >> 1) & 15;
    const int b  = bx >> 5;
    const int cb = b * 16 + jt;

    const int t    = threadIdx.x;
    const int lane = t & 31;
    const int wid  = t >> 5;
    const int slab = wid & 3;
    const int nh   = wid >> 2;
    const int nc0  = nh * 3;
    const int ncnt = nh ? 2 : 3;

    int zslot[3], boff[3], yoff[3], ymode[3], gvalid[3];
#pragma unroll
    for (int rep = 0; rep < 3; ++rep) {
        int grp = rep * 8 + wid;
        gvalid[rep] = (grp < 20);
        int g = gvalid[rep] ? grp : 0;
        int kst = g / 5;
        int nc  = g - kst * 5;
        int klo = kst * 16 + ((lane & 3) << 1);
        int n   = nc * 8 + (lane >> 2);
        int jl  = n / 10;
        int c   = n - jl * 10;
        zslot[rep] = ((kst * 5 + nc) * 32 + lane) * 2;
        boff[rep]  = jl * YSTR + klo;
        yoff[rep]  = (c >= 1 && c <= 8) ? (c - 1) * YSTR + klo : 0;
        ymode[rep] = (c == 0) ? 1 : ((c == 9) ? 2 : 0);
    }

    float acc[3][4];
#pragma unroll
    for (int a = 0; a < 3; ++a)
#pragma unroll
        for (int r = 0; r < 4; ++r) acc[a][r] = 0.0f;

    const float* Yb = Y + b * (NN * 8);
    const uint4* gA = (const uint4*)g_Aperm + (size_t)b * 8192 + ks * 4096
                      + slab * 32 + lane;
    const float ljs = -3.0f + (float)(jt * 4 + (t >> 6)) * STEP;
    const int   bkk = t & 63;
    const int   yc  = t & 7;
    const int   ykk = t >> 3;
    const float* Xb1 = X + b * NN * 2 + 1;

#define STAGE(buf, kk0)                                                       \
    do {                                                                      \
        sYt[buf][yc * YSTR + ykk]      = Yb[((kk0) + ykk) * 8 + yc];          \
        sYt[buf][yc * YSTR + ykk + 32] = Yb[((kk0) + ykk + 32) * 8 + yc];     \
        float d_ = ljs - Xb1[((kk0) + bkk) * 2];                              \
        sB[buf][(t >> 6) * YSTR + bkk] = ex2f(d_ * d_ * EX2C);                \
    } while (0)

#define BUILDZ(buf)                                                           \
    do {                                                                      \
        _Pragma("unroll")                                                     \
        for (int rep = 0; rep < 3; ++rep) {                                   \
            if (gvalid[rep]) {                                                \
                float2 b0 = *(const float2*)(sB[buf] + boff[rep]);            \
                float2 b1 = *(const float2*)(sB[buf] + boff[rep] + 8);        \
                uint2 z;                                                      \
                if (ymode[rep] == 1) {                                        \
                    z.x = pack_bf16(b0.x, b0.y);                              \
                    z.y = pack_bf16(b1.x, b1.y);                              \
                } else if (ymode[rep] == 2) {                                 \
                    z.x = 0u; z.y = 0u;                                       \
                } else {                                                      \
                    float2 y0 = *(const float2*)(sYt[buf] + yoff[rep]);       \
                    float2 y1 = *(const float2*)(sYt[buf] + yoff[rep] + 8);   \
                    z.x = pack_bf16(b0.x * y0.x, b0.y * y0.y);                \
                    z.y = pack_bf16(b1.x * y1.x, b1.y * y1.y);                \
                }                                                             \
                *(uint2*)(sZ[buf] + zslot[rep]) = z;                          \
            }                                                                 \
        }                                                                     \
    } while (0)

    STAGE(0, ks * 512);
    __syncthreads();

#pragma unroll 1
    for (int ch = 0; ch < 8; ++ch) {
        const int p = ch & 1;
        const int k1 = ks * 512 + (ch + 1) * KC;

        uint4 af[4];
#pragma unroll
        for (int kst = 0; kst < 4; ++kst)
            af[kst] = __ldg(gA + (ch * 4 + kst) * 128);

        BUILDZ(p);
        if (ch < 7) STAGE(1 - p, k1);
        __syncthreads();

#pragma unroll
        for (int kst = 0; kst < 4; ++kst) {
#pragma unroll
            for (int cc = 0; cc < 3; ++cc) {
                if (cc < ncnt) {
                    uint2 bb = *(const uint2*)(sZ[p] + ((kst * 5 + nc0 + cc) * 32 + lane) * 2);
                    MMA_BF16(acc[cc], af[kst], bb);
                }
            }
        }
    }

    // store partials (c-frag layout, ST.128 coalesced)
    float* gp = g_part + ((size_t)(ks * 256 + cb)) * 2560;
#pragma unroll
    for (int cc = 0; cc < 3; ++cc) {
        if (cc < ncnt) {
            float4 v = make_float4(acc[cc][0], acc[cc][1], acc[cc][2], acc[cc][3]);
            *(float4*)(gp + (((nc0 + cc) * 4 + slab) * 32 + lane) * 4) = v;
        }
    }

    // ---- fused reduce: last arriver of the (ks=0, ks=1) pair finishes cb ----
    __threadfence();
    if (t == 0) {
        int old = atomicAdd(&g_cnt[cb], 1);
        sLast = (old == 1);
    }
    __syncthreads();
    if (!sLast) return;
    __threadfence();

    float* sD = (float*)sZ;            // 2560 floats, alias (all mma reads done)
    const float* p0 = g_part + (size_t)cb * 2560;
    const float* p1 = g_part + (size_t)(256 + cb) * 2560;
#pragma unroll
    for (int k = 0; k < 10; ++k) {
        int idx = t + k * 256;
        sD[idx] = p0[idx] + p1[idx];
    }
    __syncthreads();

#pragma unroll
    for (int rep = 0; rep < 9; ++rep) {
        int o = t + rep * 256;
        if (o < 2304) {
            int i   = o / 36;
            int rem = o - i * 36;
            int j   = rem / 9;
            int c   = rem - j * 9;
            int sl = i >> 4, rr = i & 15, half = rr >> 3, r8 = rr & 7;
            int col  = j * 10 + c;
            int idx  = (((col >> 3) * 4 + sl) * 32 + r8 * 4 + ((col & 7) >> 1)) * 4
                       + half * 2 + (col & 1);
            int colD = j * 10;
            int idxD = (((colD >> 3) * 4 + sl) * 32 + r8 * 4 + ((colD & 7) >> 1)) * 4
                       + half * 2 + (colD & 1);
            float dens = sD[idxD];
            float v = (c == 0) ? dens : sD[idx] / (dens + 1e-6f);
            out[8192 + (size_t)(b * 4096 + i * 64 + jt * 4 + j) * 9 + c] = v;
        }
    }
    if (t == 0) g_cnt[cb] = 0;         // reset for next graph replay
}

extern "C" void kernel_launch(void* const* d_in, const int* in_sizes, int n_in,
                              void* d_out, int out_size)
{
    const float* X = (const float*)d_in[0];
    const float* Y = (const float*)d_in[1];
    float* out = (float*)d_out;

    rkhs_precomp_kernel<<<512, 256>>>(X, out);
    rkhs_mma_kernel<<<512, 256>>>(X, Y, out);
}

// round 10
// speedup vs baseline: 1.1015x; 1.1015x over previous
#include <cuda_runtime.h>
#include <cstdint>

// out[b,i,j,c] = sum_k exp(-2(li-x0k)^2)*exp(-2(lj-x1k)^2)*Yb[k,c]
// GEMM: C[64 x 640] = A[64 x 1024] * Z[1024 x 640], bf16 mma m16n8k16.
// Grid 256 = (b,jt); 512 thr = 2 warp-groups, each owns one K-half (512).
#define NB    16
#define NN    1024
#define STEP  (6.0f / 63.0f)
#define EX2C  (-2.885390081777927f)   // -2*log2(e)
#define KC    64
#define YSTR  66

// A in m16n8k16 a-frag layout, bf16x2 packed: u32 idx =
//   b*32768 + kstep*512 + slab*128 + lane*4 + q
__device__ __align__(16) uint32_t g_Aperm[NB * 64 * 4 * 32 * 4];

__device__ __forceinline__ float ex2f(float x) {
    float r; asm("ex2.approx.ftz.f32 %0, %1;" : "=f"(r) : "f"(x)); return r;
}
__device__ __forceinline__ uint32_t pack_bf16(float lo, float hi) {
    uint32_t d;
    asm("cvt.rn.bf16x2.f32 %0, %1, %2;" : "=r"(d) : "f"(hi), "f"(lo));
    return d;
}
#define MMA_BF16(d, a, bb) \
    asm volatile("mma.sync.aligned.m16n8k16.row.col.f32.bf16.bf16.f32 " \
        "{%0,%1,%2,%3}, {%4,%5,%6,%7}, {%8,%9}, {%0,%1,%2,%3};" \
        : "+f"(d[0]), "+f"(d[1]), "+f"(d[2]), "+f"(d[3]) \
        : "r"(a.x), "r"(a.y), "r"(a.z), "r"(a.w), "r"(bb.x), "r"(bb.y))

// ---------- precompute A: 4 u32 per thread, one shared X load ----------
__global__ __launch_bounds__(256)
void rkhs_precomp_kernel(const float* __restrict__ X, float* __restrict__ out)
{
    int tid = blockIdx.x * blockDim.x + threadIdx.x;
    if (tid < 4096) {
        out[tid * 2 + 0] = -3.0f + (float)(tid >> 6) * STEP;
        out[tid * 2 + 1] = -3.0f + (float)(tid & 63) * STEP;
    }
    int q     = tid & 3;
    int lane  = (tid >> 2) & 31;
    int kstep = (tid >> 7) & 63;
    int b     = tid >> 13;

    int kb = kstep * 16 + ((lane & 3) << 1) + ((q >> 1) << 3);
    float4 xx = *(const float4*)(X + (size_t)(b * NN + kb) * 2);
    int rbase = (lane >> 2) + ((q & 1) << 3);
    uint32_t* dst = g_Aperm + (b * 32768 + kstep * 512 + lane * 4 + q);
#pragma unroll
    for (int slab = 0; slab < 4; ++slab) {
        float li = -3.0f + (float)(slab * 16 + rbase) * STEP;
        float d0 = li - xx.x;
        float d1 = li - xx.z;
        dst[slab * 128] = pack_bf16(ex2f(d0 * d0 * EX2C), ex2f(d1 * d1 * EX2C));
    }
}

// ---------- main: grid 256 = b(16) x jt(16), 512 thr (2 K-groups) ----------
__global__ __launch_bounds__(512, 2)
void rkhs_mma_kernel(const float* __restrict__ X, const float* __restrict__ Y,
                     float* __restrict__ out)
{
    // per-group double buffers
    __shared__ __align__(16) uint32_t sZ[2][2][4 * 5 * 32 * 2];  // 20480 B
    __shared__ __align__(16) float    sYt[2][2][8 * YSTR];       //  8448 B
    __shared__ __align__(16) float    sB[2][2][4 * YSTR];        //  4224 B

    const int bx = blockIdx.x;
    const int jt = bx & 15;
    const int b  = bx >> 4;

    const int t    = threadIdx.x;
    const int ks   = t >> 8;            // K-group 0/1
    const int tl   = t & 255;           // local id within group
    const int lane = tl & 31;
    const int wid  = tl >> 5;           // 0..7
    const int slab = wid & 3;
    const int nh   = wid >> 2;
    const int nc0  = nh * 3;
    const int ncnt = nh ? 2 : 3;

    // hoisted Z-build constants (20 groups of kstep4 x nc5 per K-group)
    int zslot[3], boff[3], yoff[3], ymode[3], gvalid[3];
#pragma unroll
    for (int rep = 0; rep < 3; ++rep) {
        int grp = rep * 8 + wid;
        gvalid[rep] = (grp < 20);
        int g = gvalid[rep] ? grp : 0;
        int kst = g / 5;
        int nc  = g - kst * 5;
        int klo = kst * 16 + ((lane & 3) << 1);
        int n   = nc * 8 + (lane >> 2);
        int jl  = n / 10;
        int c   = n - jl * 10;
        zslot[rep] = ((kst * 5 + nc) * 32 + lane) * 2;
        boff[rep]  = jl * YSTR + klo;
        yoff[rep]  = (c >= 1 && c <= 8) ? (c - 1) * YSTR + klo : 0;
        ymode[rep] = (c == 0) ? 1 : ((c == 9) ? 2 : 0);
    }

    float acc[3][4];
#pragma unroll
    for (int a = 0; a < 3; ++a)
#pragma unroll
        for (int r = 0; r < 4; ++r) acc[a][r] = 0.0f;

    const float* Yb = Y + b * (NN * 8);
    const uint4* gA = (const uint4*)g_Aperm + (size_t)b * 8192 + ks * 4096
                      + slab * 32 + lane;
    const float ljs = -3.0f + (float)(jt * 4 + (tl >> 6)) * STEP;
    const int   bkk = tl & 63;
    const int   yc  = tl & 7;
    const int   ykk = tl >> 3;
    const float* Xb1 = X + b * NN * 2 + 1;

#define STAGE(buf, kk0)                                                       \
    do {                                                                      \
        sYt[ks][buf][yc * YSTR + ykk]      = Yb[((kk0) + ykk) * 8 + yc];      \
        sYt[ks][buf][yc * YSTR + ykk + 32] = Yb[((kk0) + ykk + 32) * 8 + yc]; \
        float d_ = ljs - Xb1[((kk0) + bkk) * 2];                              \
        sB[ks][buf][(tl >> 6) * YSTR + bkk] = ex2f(d_ * d_ * EX2C);           \
    } while (0)

#define BUILDZ(buf)                                                           \
    do {                                                                      \
        _Pragma("unroll")                                                     \
        for (int rep = 0; rep < 3; ++rep) {                                   \
            if (gvalid[rep]) {                                                \
                float2 b0 = *(const float2*)(sB[ks][buf] + boff[rep]);        \
                float2 b1 = *(const float2*)(sB[ks][buf] + boff[rep] + 8);    \
                uint2 z;                                                      \
                if (ymode[rep] == 1) {                                        \
                    z.x = pack_bf16(b0.x, b0.y);                              \
                    z.y = pack_bf16(b1.x, b1.y);                              \
                } else if (ymode[rep] == 2) {                                 \
                    z.x = 0u; z.y = 0u;                                       \
                } else {                                                      \
                    float2 y0 = *(const float2*)(sYt[ks][buf] + yoff[rep]);   \
                    float2 y1 = *(const float2*)(sYt[ks][buf] + yoff[rep] + 8);\
                    z.x = pack_bf16(b0.x * y0.x, b0.y * y0.y);                \
                    z.y = pack_bf16(b1.x * y1.x, b1.y * y1.y);                \
                }                                                             \
                *(uint2*)(sZ[ks][buf] + zslot[rep]) = z;                      \
            }                                                                 \
        }                                                                     \
    } while (0)

    STAGE(0, ks * 512);
    __syncthreads();

#pragma unroll 1
    for (int ch = 0; ch < 8; ++ch) {
        const int p = ch & 1;
        const int k1 = ks * 512 + (ch + 1) * KC;

        uint4 af[4];
#pragma unroll
        for (int kst = 0; kst < 4; ++kst)
            af[kst] = __ldg(gA + (ch * 4 + kst) * 128);

        BUILDZ(p);
        if (ch < 7) STAGE(1 - p, k1);
        __syncthreads();

#pragma unroll
        for (int kst = 0; kst < 4; ++kst) {
#pragma unroll
            for (int cc = 0; cc < 3; ++cc) {
                if (cc < ncnt) {
                    uint2 bb = *(const uint2*)(sZ[ks][p] +
                               ((kst * 5 + nc0 + cc) * 32 + lane) * 2);
                    MMA_BF16(acc[cc], af[kst], bb);
                }
            }
        }
    }

    // ---- intra-CTA cross-group reduce + normalize + store ----
    __syncthreads();                     // all mma reads of sZ done
    float* sD = (float*)sZ;              // 2560 floats alias (sZ[0] region)

    if (ks == 1) {                       // group 1 stores its accs
#pragma unroll
        for (int cc = 0; cc < 3; ++cc) {
            if (cc < ncnt) {
                float4 v = make_float4(acc[cc][0], acc[cc][1], acc[cc][2], acc[cc][3]);
                *(float4*)(sD + (((nc0 + cc) * 4 + slab) * 32 + lane) * 4) = v;
            }
        }
    }
    __syncthreads();
    if (ks == 0) {                       // group 0 adds in place (unique slot)
#pragma unroll
        for (int cc = 0; cc < 3; ++cc) {
            if (cc < ncnt) {
                float4* p4 = (float4*)(sD + (((nc0 + cc) * 4 + slab) * 32 + lane) * 4);
                float4 v = *p4;
                v.x += acc[cc][0]; v.y += acc[cc][1];
                v.z += acc[cc][2]; v.w += acc[cc][3];
                *p4 = v;
            }
        }
    }
    __syncthreads();

    // 2304 outputs with frag->(i,j,c) inverse mapping
#pragma unroll
    for (int rep = 0; rep < 5; ++rep) {
        int o = t + rep * 512;
        if (o < 2304) {
            int i   = o / 36;
            int rem = o - i * 36;
            int j   = rem / 9;
            int c   = rem - j * 9;
            int sl = i >> 4, rr = i & 15, half = rr >> 3, r8 = rr & 7;
            int col  = j * 10 + c;
            int idx  = (((col >> 3) * 4 + sl) * 32 + r8 * 4 + ((col & 7) >> 1)) * 4
                       + half * 2 + (col & 1);
            int colD = j * 10;
            int idxD = (((colD >> 3) * 4 + sl) * 32 + r8 * 4 + ((colD & 7) >> 1)) * 4
                       + half * 2 + (colD & 1);
            float dens = sD[idxD];
            float v = (c == 0) ? dens : sD[idx] / (dens + 1e-6f);
            out[8192 + (size_t)(b * 4096 + i * 64 + jt * 4 + j) * 9 + c] = v;
        }
    }
}

extern "C" void kernel_launch(void* const* d_in, const int* in_sizes, int n_in,
                              void* d_out, int out_size)
{
    const float* X = (const float*)d_in[0];
    const float* Y = (const float*)d_in[1];
    float* out = (float*)d_out;

    rkhs_precomp_kernel<<<512, 256>>>(X, out);
    rkhs_mma_kernel<<<256, 512>>>(X, Y, out);
}